// round 13
// baseline (speedup 1.0000x reference)
#include <cuda_runtime.h>
#include <stdint.h>

#define N_FFT  4096
#define NBINS  2049
#define NMICS  8
#define BATCH  16
#define NPAIR  28
#define NLAG   81
#define FFT_THREADS 512      // xcorr
#define WH_THREADS  256      // whiten (split kernel)

// padded smem index: conflict-free / near-conflict-free for patterns used
#define SP(i) ((i) + ((i) >> 4) + ((i) >> 8))

// ----- 4096-pt iFFT (xcorr) constants -----
#define SMEM_PAD   4368
#define NTW        1360
#define XC_SMEM    ((SMEM_PAD + 3 * NTW) * sizeof(float2))    // ~67.6 KB

// ----- split whiten constants: each CTA holds 2 subs x 512 = 1024 elems -----
#define N2         2048
#define WPAD       1104                   // SP(1023)=1089 -> round up
#define NTWW       168                    // Q=128(128) + Q=32(32) + Q=8(8)
#define WH_SMEM    ((WPAD + 3 * NTWW) * sizeof(float2))       // ~12.9 KB

__device__ float2 g_W[BATCH * NMICS * NBINS];        // whitened spectra (natural order)
__device__ float  g_cc[NPAIR * NLAG * BATCH];        // cc table [p][t][b16]
__device__ unsigned long long g_best[BATCH];
__device__ int    g_done;

// PDL primitives
__device__ __forceinline__ void pdl_wait()    { asm volatile("griddepcontrol.wait;" ::: "memory"); }
__device__ __forceinline__ void pdl_trigger() { asm volatile("griddepcontrol.launch_dependents;" ::: "memory"); }

// base-4 digit reversal of 12-bit index (involution) — 4096 iFFT output perm
__device__ __forceinline__ int dr12(int i)
{
    unsigned x = __brev((unsigned)i) >> 20;
    return (int)(((x & 0xAAAu) >> 1) | ((x & 0x555u) << 1));
}

// DIF output position within a 512-pt sub-chain (stages Q=128,32,8 + 8-pt tail)
__device__ __forceinline__ int perm512(int t)
{
    return ((t & 3) << 7) | (((t >> 2) & 3) << 5) | (((t >> 4) & 3) << 3)
         | (((t >> 6) & 3) << 1) | (t >> 8);
}

__device__ __forceinline__ float2 cmul(float2 a, float2 b)
{
    return make_float2(a.x * b.x - a.y * b.y, a.x * b.y + a.y * b.x);
}

// ===========================================================================
// Kernel 1 (SPLIT): forward real-4096 FFT via 2048-pt complex FFT, TWO CTAs
// per signal. Radix-4 DIF stage 1 (Q=512) separates the transform into 4
// independent 512-pt subs by k mod 4. CTA half=0 keeps subs {0,2} (even rfft
// bins); half=1 keeps subs {1,3} (odd bins). Conjugate-mirror untangle pairs
// (k, 2048-k) preserve parity -> fully CTA-local. 256 blocks x 256 threads.
// ===========================================================================
__global__ void __launch_bounds__(WH_THREADS) k_fft_whiten(const float* __restrict__ sig)
{
    extern __shared__ float2 dyn[];
    float2* s  = dyn;                 // 1024 padded (2 subs x 512)
    float2* tw = dyn + WPAD;          // 3 * NTWW

    const int tid  = threadIdx.x;
    const int sgn  = blockIdx.x >> 1;      // signal (batch*NMICS + mic)
    const int half = blockIdx.x & 1;       // residue group: {0,2} or {1,3}

    // twiddles for sub-FFT stages Q=128,32,8 (forward sign)
    if (tid < NTWW) {
        int Q, k;
        if      (tid < 128) { Q = 128; k = tid; }
        else if (tid < 160) { Q = 32;  k = tid - 128; }
        else                { Q = 8;   k = tid - 160; }
        float th = -3.14159265358979323846f * (float)k / (2.0f * (float)Q);
        float s1, c1, s2, c2, s3, c3;
        __sincosf(th,        &s1, &c1);
        __sincosf(th * 2.0f, &s2, &c2);
        __sincosf(th * 3.0f, &s3, &c3);
        tw[tid]            = make_float2(c1, s1);
        tw[tid + NTWW]     = make_float2(c2, s2);
        tw[tid + 2 * NTWW] = make_float2(c3, s3);
    }

    // Stage 1 (Q=512) straight from gmem: z[n] = x[2n] + i*x[2n+1].
    // Keep only residues rA=half (-> region [0,512)) and rB=half+2 (-> [512,1024)).
    const float2* xz = (const float2*)(sig + (size_t)sgn * N_FFT);
    #pragma unroll
    for (int u = 0; u < 2; ++u) {
        int j = tid + u * WH_THREADS;
        float2 a0 = xz[j];
        float2 a1 = xz[j + 512];
        float2 a2 = xz[j + 1024];
        float2 a3 = xz[j + 1536];

        float2 A = make_float2(a0.x + a2.x, a0.y + a2.y);
        float2 B = make_float2(a0.x - a2.x, a0.y - a2.y);
        float2 C = make_float2(a1.x + a3.x, a1.y + a3.y);
        float2 D = make_float2(a1.x - a3.x, a1.y - a3.y);

        float th = -6.283185307179586f * (float)j / 2048.0f;   // -2*pi*j/2048
        if (half == 0) {
            // r=0: A+C (tw=1);  r=2: A-C (tw=W^{2j})
            float sn, cs;
            __sincosf(th * 2.0f, &sn, &cs);
            s[SP(j)]       = make_float2(A.x + C.x, A.y + C.y);
            s[SP(512 + j)] = cmul(make_float2(A.x - C.x, A.y - C.y),
                                  make_float2(cs, sn));
        } else {
            // r=1: B - iD (tw=W^j);  r=3: B + iD (tw=W^{3j})
            float sn, cs;
            __sincosf(th, &sn, &cs);
            float2 w1 = make_float2(cs, sn);
            float2 w2 = cmul(w1, w1);
            float2 w3 = cmul(w2, w1);
            s[SP(j)]       = cmul(make_float2(B.x + D.y, B.y - D.x), w1);
            s[SP(512 + j)] = cmul(make_float2(B.x - D.y, B.y + D.x), w3);
        }
    }
    __syncthreads();

    // Two independent 512-pt FFTs: table stages Q=128,32,8 (1 bf/thread).
    const int OFF[3] = {0, 128, 160};
    #pragma unroll
    for (int st = 0; st < 3; ++st) {
        const int lg = 7 - 2 * st;
        const int Q  = 1 << lg;
        int sub = tid >> 7;                  // 0 or 1
        int j   = tid & 127;
        int k   = j & (Q - 1);
        int base = sub * 512 + ((j >> lg) << (lg + 2)) + k;

        float2 a0 = s[SP(base)];
        float2 a1 = s[SP(base + Q)];
        float2 a2 = s[SP(base + 2 * Q)];
        float2 a3 = s[SP(base + 3 * Q)];

        float2 A = make_float2(a0.x + a2.x, a0.y + a2.y);
        float2 B = make_float2(a0.x - a2.x, a0.y - a2.y);
        float2 C = make_float2(a1.x + a3.x, a1.y + a3.y);
        float2 D = make_float2(a1.x - a3.x, a1.y - a3.y);

        float2 y0 = make_float2(A.x + C.x, A.y + C.y);
        float2 y1 = make_float2(B.x + D.y, B.y - D.x);   // forward: B - iD
        float2 y2 = make_float2(A.x - C.x, A.y - C.y);
        float2 y3 = make_float2(B.x - D.y, B.y + D.x);   // forward: B + iD

        int ti = OFF[st] + k;
        s[SP(base)]         = y0;
        s[SP(base + Q)]     = cmul(y1, tw[ti]);
        s[SP(base + 2 * Q)] = cmul(y2, tw[ti + NTWW]);
        s[SP(base + 3 * Q)] = cmul(y3, tw[ti + 2 * NTWW]);
        __syncthreads();
    }

    // fused 8-pt tail (Q=2 radix-4 const twiddles + radix-2), threads 0-127,
    // groups of 8 contiguous elements (each group inside one sub).
    if (tid < 128) {
        const float RT = 0.70710678118654752f;
        float2 v[8];
        const int e0 = tid * 8;
        #pragma unroll
        for (int i = 0; i < 8; ++i) v[i] = s[SP(e0 + i)];

        {
            float2 A = make_float2(v[0].x + v[4].x, v[0].y + v[4].y);
            float2 B = make_float2(v[0].x - v[4].x, v[0].y - v[4].y);
            float2 C = make_float2(v[2].x + v[6].x, v[2].y + v[6].y);
            float2 D = make_float2(v[2].x - v[6].x, v[2].y - v[6].y);
            v[0] = make_float2(A.x + C.x, A.y + C.y);
            v[2] = make_float2(B.x + D.y, B.y - D.x);
            v[4] = make_float2(A.x - C.x, A.y - C.y);
            v[6] = make_float2(B.x - D.y, B.y + D.x);
        }
        {
            float2 A = make_float2(v[1].x + v[5].x, v[1].y + v[5].y);
            float2 B = make_float2(v[1].x - v[5].x, v[1].y - v[5].y);
            float2 C = make_float2(v[3].x + v[7].x, v[3].y + v[7].y);
            float2 D = make_float2(v[3].x - v[7].x, v[3].y - v[7].y);
            float2 y1 = make_float2(B.x + D.y, B.y - D.x);
            float2 y2 = make_float2(A.x - C.x, A.y - C.y);
            float2 y3 = make_float2(B.x - D.y, B.y + D.x);
            v[1] = make_float2(A.x + C.x, A.y + C.y);
            v[3] = make_float2((y1.x + y1.y) * RT, (y1.y - y1.x) * RT);
            v[5] = make_float2(y2.y, -y2.x);
            v[7] = make_float2((y3.y - y3.x) * RT, -(y3.x + y3.y) * RT);
        }
        #pragma unroll
        for (int i = 0; i < 4; ++i) {
            float2 a = v[2 * i], b = v[2 * i + 1];
            v[2 * i]     = make_float2(a.x + b.x, a.y + b.y);
            v[2 * i + 1] = make_float2(a.x - b.x, a.y - b.y);
        }
        #pragma unroll
        for (int i = 0; i < 8; ++i) s[SP(e0 + i)] = v[i];
    }
    __syncthreads();

    // untangle + whiten: this CTA owns bins with k%2 == half.
    // Z[m] lives at region (m&3)>>1, position perm512(m>>2).
    float2* w = g_W + (size_t)sgn * NBINS;
    for (int k = 2 * tid + half; k <= N2 / 2; k += 2 * WH_THREADS) {
        int m  = k;                          // k <= 1024 < 2048
        int mc = (N2 - k) & (N2 - 1);
        float2 Zk = s[SP(((m  & 3) >> 1) * 512 + perm512(m  >> 2))];
        float2 Zc = s[SP(((mc & 3) >> 1) * 512 + perm512(mc >> 2))];

        float Ax = Zk.x + Zc.x, Ay = Zk.y - Zc.y;
        float Bx = Zk.x - Zc.x, By = Zk.y + Zc.y;

        float sn, cs;
        __sincosf(-3.14159265358979323846f * (float)k / (float)N2, &sn, &cs);
        float t1 = cs * By + sn * Bx;
        float t2 = cs * Bx - sn * By;

        float X0x = Ax + t1, X0y = Ay - t2;
        float X1x = Ax - t1, X1y = -(Ay + t2);

        float i0 = rsqrtf(X0x * X0x + X0y * X0y + 1e-24f);
        float i1 = rsqrtf(X1x * X1x + X1y * X1y + 1e-24f);
        w[k]      = make_float2(X0x * i0, X0y * i0);
        w[N2 - k] = make_float2(X1x * i1, X1y * i1);
    }

    if (tid == 0) pdl_trigger();
}

// ===========================================================================
// 4096-pt radix-4 DIF inverse FFT machinery (round-12, proven)
// ===========================================================================
__device__ __forceinline__ void gen_twiddles(float2* tw, int tid)
{
    for (int gid = tid; gid < NTW; gid += FFT_THREADS) {
        int Q, k;
        if      (gid < 1024) { Q = 1024; k = gid; }
        else if (gid < 1280) { Q = 256;  k = gid - 1024; }
        else if (gid < 1344) { Q = 64;   k = gid - 1280; }
        else                 { Q = 16;   k = gid - 1344; }
        float th = -3.14159265358979323846f * (float)k / (2.0f * (float)Q);
        float s1, c1, s2, c2, s3, c3;
        __sincosf(th,        &s1, &c1);
        __sincosf(th * 2.0f, &s2, &c2);
        __sincosf(th * 3.0f, &s3, &c3);
        tw[gid]           = make_float2(c1, s1);
        tw[gid + NTW]     = make_float2(c2, s2);
        tw[gid + 2 * NTW] = make_float2(c3, s3);
    }
}

__device__ __forceinline__ void ifft4096_dif(float2* s, const float2* tw, int tid)
{
    const int OFF[4] = {0, 1024, 1280, 1344};
    #pragma unroll
    for (int st = 0; st < 4; ++st) {
        const int lg = 10 - 2 * st;
        const int Q  = 1 << lg;
        #pragma unroll
        for (int u = 0; u < 2; ++u) {
            int j    = tid + u * FFT_THREADS;
            int k    = j & (Q - 1);
            int base = ((j >> lg) << (lg + 2)) + k;

            float2 a0 = s[SP(base)];
            float2 a1 = s[SP(base + Q)];
            float2 a2 = s[SP(base + 2 * Q)];
            float2 a3 = s[SP(base + 3 * Q)];

            float2 A = make_float2(a0.x + a2.x, a0.y + a2.y);
            float2 B = make_float2(a0.x - a2.x, a0.y - a2.y);
            float2 C = make_float2(a1.x + a3.x, a1.y + a3.y);
            float2 D = make_float2(a1.x - a3.x, a1.y - a3.y);

            float2 y0 = make_float2(A.x + C.x, A.y + C.y);
            float2 y1 = make_float2(B.x - D.y, B.y + D.x);
            float2 y2 = make_float2(A.x - C.x, A.y - C.y);
            float2 y3 = make_float2(B.x + D.y, B.y - D.x);

            int ti = OFF[st] + k;
            float2 w1 = tw[ti];           w1.y = -w1.y;
            float2 w2 = tw[ti + NTW];     w2.y = -w2.y;
            float2 w3 = tw[ti + 2 * NTW]; w3.y = -w3.y;

            s[SP(base)]         = y0;
            s[SP(base + Q)]     = cmul(y1, w1);
            s[SP(base + 2 * Q)] = cmul(y2, w2);
            s[SP(base + 3 * Q)] = cmul(y3, w3);
        }
        __syncthreads();
    }

    if (tid < 256) {
        const float CS[10] = { 1.f,  0.92387953f,  0.70710678f,  0.38268343f,  0.f,
                              -0.38268343f, -0.70710678f, -0.92387953f, -1.f, -0.92387953f};
        const float SN[10] = { 0.f, -0.38268343f, -0.70710678f, -0.92387953f, -1.f,
                              -0.92387953f, -0.70710678f, -0.38268343f,  0.f,  0.38268343f};
        const float sg = -1.0f;
        float2 v[16];
        const int e0 = 16 * tid;
        #pragma unroll
        for (int m = 0; m < 16; ++m) v[m] = s[SP(e0 + m)];

        #pragma unroll
        for (int m = 0; m < 4; ++m) {
            float2 p = v[m], q = v[m + 4], r = v[m + 8], w = v[m + 12];
            float2 A = make_float2(p.x + r.x, p.y + r.y);
            float2 B = make_float2(p.x - r.x, p.y - r.y);
            float2 C = make_float2(q.x + w.x, q.y + w.y);
            float2 D = make_float2(q.x - w.x, q.y - w.y);
            float2 y0 = make_float2(A.x + C.x, A.y + C.y);
            float2 y1 = make_float2(B.x + sg * D.y, B.y - sg * D.x);
            float2 y2 = make_float2(A.x - C.x, A.y - C.y);
            float2 y3 = make_float2(B.x - sg * D.y, B.y + sg * D.x);
            float2 w1 = make_float2(CS[m],     sg * SN[m]);
            float2 w2 = make_float2(CS[2 * m], sg * SN[2 * m]);
            float2 w3 = make_float2(CS[3 * m], sg * SN[3 * m]);
            v[m]      = y0;
            v[m + 4]  = cmul(y1, w1);
            v[m + 8]  = cmul(y2, w2);
            v[m + 12] = cmul(y3, w3);
        }
        #pragma unroll
        for (int h = 0; h < 4; ++h) {
            float2 p = v[4*h], q = v[4*h+1], r = v[4*h+2], w = v[4*h+3];
            float2 A = make_float2(p.x + r.x, p.y + r.y);
            float2 B = make_float2(p.x - r.x, p.y - r.y);
            float2 C = make_float2(q.x + w.x, q.y + w.y);
            float2 D = make_float2(q.x - w.x, q.y - w.y);
            v[4*h]   = make_float2(A.x + C.x, A.y + C.y);
            v[4*h+1] = make_float2(B.x + sg * D.y, B.y - sg * D.x);
            v[4*h+2] = make_float2(A.x - C.x, A.y - C.y);
            v[4*h+3] = make_float2(B.x - sg * D.y, B.y + sg * D.x);
        }
        #pragma unroll
        for (int m = 0; m < 16; ++m) s[SP(e0 + m)] = v[m];
    }
    __syncthreads();
}

// ===========================================================================
// Kernel 2: cross-spectrum + inverse FFT, two pairs per iFFT.
// 224 blocks x 512 threads. PDL both sides. (round-12, proven)
// ===========================================================================
__global__ void __launch_bounds__(FFT_THREADS) k_xcorr(const int* __restrict__ comb)
{
    extern __shared__ float2 dyn[];
    float2* s  = dyn;
    float2* tw = dyn + SMEM_PAD;

    const int tid = threadIdx.x;
    if (blockIdx.x == 0 && tid == 0) {
        g_done = 0;
        #pragma unroll
        for (int b = 0; b < BATCH; ++b) g_best[b] = 0ull;
    }

    const int q0 = blockIdx.x * 2, q1 = q0 + 1;
    const int b0 = q0 / NPAIR, p0 = q0 % NPAIR;
    const int b1 = q1 / NPAIR, p1 = q1 % NPAIR;

    const int ia0 = comb[2 * p0], ib0 = comb[2 * p0 + 1];
    const int ia1 = comb[2 * p1], ib1 = comb[2 * p1 + 1];

    gen_twiddles(tw, tid);          // overlaps with whiten via PDL

    pdl_wait();                     // g_W must be complete beyond here

    const float2* Wa0 = g_W + (size_t)(b0 * NMICS + ia0) * NBINS;
    const float2* Wb0 = g_W + (size_t)(b0 * NMICS + ib0) * NBINS;
    const float2* Wa1 = g_W + (size_t)(b1 * NMICS + ia1) * NBINS;
    const float2* Wb1 = g_W + (size_t)(b1 * NMICS + ib1) * NBINS;

    for (int k = tid; k <= N_FFT / 2; k += FFT_THREADS) {
        float2 a0 = Wa0[k], c0 = Wb0[k];
        float x1r = a0.x * c0.x + a0.y * c0.y;
        float x1i = a0.y * c0.x - a0.x * c0.y;
        float2 a1 = Wa1[k], c1 = Wb1[k];
        float x2r = a1.x * c1.x + a1.y * c1.y;
        float x2i = a1.y * c1.x - a1.x * c1.y;

        s[SP(k)] = make_float2(x1r - x2i, x1i + x2r);
        if (k > 0 && k < N_FFT / 2)
            s[SP(N_FFT - k)] = make_float2(x1r + x2i, x2r - x1i);
    }
    __syncthreads();

    ifft4096_dif(s, tw, tid);

    if (tid < NLAG) {
        int idx = (tid + (N_FFT - 40)) & (N_FFT - 1);
        float2 v = s[SP(dr12(idx))];
        g_cc[(p0 * NLAG + tid) * BATCH + b0] = v.x;
        g_cc[(p1 * NLAG + tid) * BATCH + b1] = v.y;
    }

    if (tid == 0) pdl_trigger();
}

// ===========================================================================
// Kernel 3: SRP accumulation + argmax + fused final decode. (round-12, proven)
// ===========================================================================
__device__ __forceinline__ unsigned int fkey(float f)
{
    unsigned int b = __float_as_uint(f);
    return (b & 0x80000000u) ? ~b : (b | 0x80000000u);
}

__global__ void __launch_bounds__(256) k_srp(const int* __restrict__ tau, int G,
                                             const float* __restrict__ grid_x,
                                             const float* __restrict__ cen,
                                             float* __restrict__ out)
{
    __shared__ unsigned long long sbest[BATCH];
    __shared__ int s_last;
    const int tid = threadIdx.x;
    if (tid < BATCH) sbest[tid] = 0ull;
    if (tid == 0) s_last = 0;
    __syncthreads();

    pdl_wait();                     // g_cc (and g_best reset) complete beyond here

    const int tIdx = blockIdx.x * 256 + tid;
    const int g    = tIdx >> 3;
    const int bp   = tid & 7;

    unsigned long long k0 = 0ull, k1 = 0ull;

    if (g < G) {
        float2 pw = make_float2(0.0f, 0.0f);
        const int4* trow = (const int4*)(tau + (size_t)g * NPAIR);
        #pragma unroll
        for (int pc = 0; pc < NPAIR / 4; ++pc) {
            int4 tv = trow[pc];
            int ts[4] = { tv.x, tv.y, tv.z, tv.w };
            #pragma unroll
            for (int e = 0; e < 4; ++e) {
                int p = pc * 4 + e;
                float2 r = *(const float2*)(g_cc + (p * NLAG + ts[e]) * BATCH + bp * 2);
                pw.x += r.x; pw.y += r.y;
            }
        }
        const unsigned int gk = ~(unsigned int)g;
        k0 = ((unsigned long long)fkey(pw.x) << 32) | gk;
        k1 = ((unsigned long long)fkey(pw.y) << 32) | gk;
    }

    #pragma unroll
    for (int off = 8; off < 32; off <<= 1) {
        unsigned long long o0 = __shfl_xor_sync(0xFFFFFFFFu, k0, off);
        unsigned long long o1 = __shfl_xor_sync(0xFFFFFFFFu, k1, off);
        if (o0 > k0) k0 = o0;
        if (o1 > k1) k1 = o1;
    }
    if ((tid & 31) < 8) {
        atomicMax(&sbest[bp * 2],     k0);
        atomicMax(&sbest[bp * 2 + 1], k1);
    }
    __syncthreads();

    if (tid < BATCH) {
        atomicMax(&g_best[tid], sbest[tid]);
        __threadfence();
    }
    __syncthreads();
    if (tid == 0) {
        int ticket = atomicAdd(&g_done, 1);
        if (ticket == (int)gridDim.x - 1) { __threadfence(); s_last = 1; }
    }
    __syncthreads();
    if (s_last && tid < BATCH) {
        unsigned long long v = atomicMax(&g_best[tid], 0ull);
        unsigned int idx = ~(unsigned int)(v & 0xFFFFFFFFull);
        #pragma unroll
        for (int j = 0; j < 3; ++j)
            out[tid * 3 + j] = grid_x[(size_t)idx * 3 + j] - cen[j];
    }
}

// ---------------------------------------------------------------------------
extern "C" void kernel_launch(void* const* d_in, const int* in_sizes, int n_in,
                              void* d_out, int out_size)
{
    const float* signal = (const float*)d_in[0];
    const float* grid_x = (const float*)d_in[1];
    const int*   tau    = (const int*)d_in[2];
    const int*   comb   = (const int*)d_in[3];
    const float* cen    = (const float*)d_in[4];

    const int G = in_sizes[1] / 3;

    cudaFuncSetAttribute(k_xcorr, cudaFuncAttributeMaxDynamicSharedMemorySize,
                         (int)XC_SMEM);

    // primary: normal launch (now 256 blocks x 256 threads)
    k_fft_whiten<<<BATCH * NMICS * 2, WH_THREADS, WH_SMEM>>>(signal);

    // dependents: PDL — prologue overlaps primary; wait gates the data reads.
    cudaLaunchAttribute attr[1];
    attr[0].id = cudaLaunchAttributeProgrammaticStreamSerialization;
    attr[0].val.programmaticStreamSerializationAllowed = 1;

    {
        cudaLaunchConfig_t cfg = {};
        cfg.gridDim  = dim3(BATCH * NPAIR / 2, 1, 1);
        cfg.blockDim = dim3(FFT_THREADS, 1, 1);
        cfg.dynamicSmemBytes = XC_SMEM;
        cfg.stream = 0;
        cfg.attrs = attr;
        cfg.numAttrs = 1;
        cudaLaunchKernelEx(&cfg, k_xcorr, comb);
    }
    {
        cudaLaunchConfig_t cfg = {};
        cfg.gridDim  = dim3((8 * G + 255) / 256, 1, 1);
        cfg.blockDim = dim3(256, 1, 1);
        cfg.dynamicSmemBytes = 0;
        cfg.stream = 0;
        cfg.attrs = attr;
        cfg.numAttrs = 1;
        cudaLaunchKernelEx(&cfg, k_srp, tau, G, grid_x, cen, (float*)d_out);
    }
}

// round 14
// speedup vs baseline: 1.0222x; 1.0222x over previous
#include <cuda_runtime.h>
#include <stdint.h>

#define N_FFT  4096
#define NBINS  2049
#define NMICS  8
#define BATCH  16
#define NPAIR  28
#define NLAG   81
#define FFT_THREADS 512      // xcorr
#define WH_THREADS  256      // whiten (split kernel)

// padded smem index: conflict-free / near-conflict-free for patterns used
#define SP(i) ((i) + ((i) >> 4) + ((i) >> 8))

// ----- 4096-pt iFFT (xcorr) constants -----
// Only the Q=1024 W^1 table is stored (1024 entries); stages Q=256/64/16
// index entry k*4^st, and W^2/W^3 are computed in-loop. smem 67.6->43.1 KB
// => multi-block co-residency per SM (was 1 block/SM).
#define SMEM_PAD   4368
#define NTW        1024
#define XC_SMEM    ((SMEM_PAD + NTW) * sizeof(float2))        // ~43.1 KB

// ----- split whiten constants: each CTA holds 2 subs x 512 = 1024 elems -----
#define N2         2048
#define WPAD       1104                   // SP(1023)=1089 -> round up
#define NTWW       168                    // Q=128(128) + Q=32(32) + Q=8(8)
#define WH_SMEM    ((WPAD + 3 * NTWW) * sizeof(float2))       // ~12.9 KB

__device__ float2 g_W[BATCH * NMICS * NBINS];        // whitened spectra (natural order)
__device__ float  g_cc[NPAIR * NLAG * BATCH];        // cc table [p][t][b16]
__device__ unsigned long long g_best[BATCH];
__device__ int    g_done;

// PDL primitives
__device__ __forceinline__ void pdl_wait()    { asm volatile("griddepcontrol.wait;" ::: "memory"); }
__device__ __forceinline__ void pdl_trigger() { asm volatile("griddepcontrol.launch_dependents;" ::: "memory"); }

// base-4 digit reversal of 12-bit index (involution) — 4096 iFFT output perm
__device__ __forceinline__ int dr12(int i)
{
    unsigned x = __brev((unsigned)i) >> 20;
    return (int)(((x & 0xAAAu) >> 1) | ((x & 0x555u) << 1));
}

// DIF output position within a 512-pt sub-chain (stages Q=128,32,8 + 8-pt tail)
__device__ __forceinline__ int perm512(int t)
{
    return ((t & 3) << 7) | (((t >> 2) & 3) << 5) | (((t >> 4) & 3) << 3)
         | (((t >> 6) & 3) << 1) | (t >> 8);
}

__device__ __forceinline__ float2 cmul(float2 a, float2 b)
{
    return make_float2(a.x * b.x - a.y * b.y, a.x * b.y + a.y * b.x);
}

// ===========================================================================
// Kernel 1 (SPLIT): forward real-4096 FFT via 2048-pt complex FFT, TWO CTAs
// per signal (round-13, proven correct, 7.33us). 256 blocks x 256 threads.
// ===========================================================================
__global__ void __launch_bounds__(WH_THREADS) k_fft_whiten(const float* __restrict__ sig)
{
    extern __shared__ float2 dyn[];
    float2* s  = dyn;                 // 1024 padded (2 subs x 512)
    float2* tw = dyn + WPAD;          // 3 * NTWW

    const int tid  = threadIdx.x;
    const int sgn  = blockIdx.x >> 1;      // signal (batch*NMICS + mic)
    const int half = blockIdx.x & 1;       // residue group: {0,2} or {1,3}

    if (tid < NTWW) {
        int Q, k;
        if      (tid < 128) { Q = 128; k = tid; }
        else if (tid < 160) { Q = 32;  k = tid - 128; }
        else                { Q = 8;   k = tid - 160; }
        float th = -3.14159265358979323846f * (float)k / (2.0f * (float)Q);
        float s1, c1, s2, c2, s3, c3;
        __sincosf(th,        &s1, &c1);
        __sincosf(th * 2.0f, &s2, &c2);
        __sincosf(th * 3.0f, &s3, &c3);
        tw[tid]            = make_float2(c1, s1);
        tw[tid + NTWW]     = make_float2(c2, s2);
        tw[tid + 2 * NTWW] = make_float2(c3, s3);
    }

    const float2* xz = (const float2*)(sig + (size_t)sgn * N_FFT);
    #pragma unroll
    for (int u = 0; u < 2; ++u) {
        int j = tid + u * WH_THREADS;
        float2 a0 = xz[j];
        float2 a1 = xz[j + 512];
        float2 a2 = xz[j + 1024];
        float2 a3 = xz[j + 1536];

        float2 A = make_float2(a0.x + a2.x, a0.y + a2.y);
        float2 B = make_float2(a0.x - a2.x, a0.y - a2.y);
        float2 C = make_float2(a1.x + a3.x, a1.y + a3.y);
        float2 D = make_float2(a1.x - a3.x, a1.y - a3.y);

        float th = -6.283185307179586f * (float)j / 2048.0f;
        if (half == 0) {
            float sn, cs;
            __sincosf(th * 2.0f, &sn, &cs);
            s[SP(j)]       = make_float2(A.x + C.x, A.y + C.y);
            s[SP(512 + j)] = cmul(make_float2(A.x - C.x, A.y - C.y),
                                  make_float2(cs, sn));
        } else {
            float sn, cs;
            __sincosf(th, &sn, &cs);
            float2 w1 = make_float2(cs, sn);
            float2 w2 = cmul(w1, w1);
            float2 w3 = cmul(w2, w1);
            s[SP(j)]       = cmul(make_float2(B.x + D.y, B.y - D.x), w1);
            s[SP(512 + j)] = cmul(make_float2(B.x - D.y, B.y + D.x), w3);
        }
    }
    __syncthreads();

    const int OFF[3] = {0, 128, 160};
    #pragma unroll
    for (int st = 0; st < 3; ++st) {
        const int lg = 7 - 2 * st;
        const int Q  = 1 << lg;
        int sub = tid >> 7;
        int j   = tid & 127;
        int k   = j & (Q - 1);
        int base = sub * 512 + ((j >> lg) << (lg + 2)) + k;

        float2 a0 = s[SP(base)];
        float2 a1 = s[SP(base + Q)];
        float2 a2 = s[SP(base + 2 * Q)];
        float2 a3 = s[SP(base + 3 * Q)];

        float2 A = make_float2(a0.x + a2.x, a0.y + a2.y);
        float2 B = make_float2(a0.x - a2.x, a0.y - a2.y);
        float2 C = make_float2(a1.x + a3.x, a1.y + a3.y);
        float2 D = make_float2(a1.x - a3.x, a1.y - a3.y);

        float2 y0 = make_float2(A.x + C.x, A.y + C.y);
        float2 y1 = make_float2(B.x + D.y, B.y - D.x);
        float2 y2 = make_float2(A.x - C.x, A.y - C.y);
        float2 y3 = make_float2(B.x - D.y, B.y + D.x);

        int ti = OFF[st] + k;
        s[SP(base)]         = y0;
        s[SP(base + Q)]     = cmul(y1, tw[ti]);
        s[SP(base + 2 * Q)] = cmul(y2, tw[ti + NTWW]);
        s[SP(base + 3 * Q)] = cmul(y3, tw[ti + 2 * NTWW]);
        __syncthreads();
    }

    if (tid < 128) {
        const float RT = 0.70710678118654752f;
        float2 v[8];
        const int e0 = tid * 8;
        #pragma unroll
        for (int i = 0; i < 8; ++i) v[i] = s[SP(e0 + i)];

        {
            float2 A = make_float2(v[0].x + v[4].x, v[0].y + v[4].y);
            float2 B = make_float2(v[0].x - v[4].x, v[0].y - v[4].y);
            float2 C = make_float2(v[2].x + v[6].x, v[2].y + v[6].y);
            float2 D = make_float2(v[2].x - v[6].x, v[2].y - v[6].y);
            v[0] = make_float2(A.x + C.x, A.y + C.y);
            v[2] = make_float2(B.x + D.y, B.y - D.x);
            v[4] = make_float2(A.x - C.x, A.y - C.y);
            v[6] = make_float2(B.x - D.y, B.y + D.x);
        }
        {
            float2 A = make_float2(v[1].x + v[5].x, v[1].y + v[5].y);
            float2 B = make_float2(v[1].x - v[5].x, v[1].y - v[5].y);
            float2 C = make_float2(v[3].x + v[7].x, v[3].y + v[7].y);
            float2 D = make_float2(v[3].x - v[7].x, v[3].y - v[7].y);
            float2 y1 = make_float2(B.x + D.y, B.y - D.x);
            float2 y2 = make_float2(A.x - C.x, A.y - C.y);
            float2 y3 = make_float2(B.x - D.y, B.y + D.x);
            v[1] = make_float2(A.x + C.x, A.y + C.y);
            v[3] = make_float2((y1.x + y1.y) * RT, (y1.y - y1.x) * RT);
            v[5] = make_float2(y2.y, -y2.x);
            v[7] = make_float2((y3.y - y3.x) * RT, -(y3.x + y3.y) * RT);
        }
        #pragma unroll
        for (int i = 0; i < 4; ++i) {
            float2 a = v[2 * i], b = v[2 * i + 1];
            v[2 * i]     = make_float2(a.x + b.x, a.y + b.y);
            v[2 * i + 1] = make_float2(a.x - b.x, a.y - b.y);
        }
        #pragma unroll
        for (int i = 0; i < 8; ++i) s[SP(e0 + i)] = v[i];
    }
    __syncthreads();

    float2* w = g_W + (size_t)sgn * NBINS;
    for (int k = 2 * tid + half; k <= N2 / 2; k += 2 * WH_THREADS) {
        int m  = k;
        int mc = (N2 - k) & (N2 - 1);
        float2 Zk = s[SP(((m  & 3) >> 1) * 512 + perm512(m  >> 2))];
        float2 Zc = s[SP(((mc & 3) >> 1) * 512 + perm512(mc >> 2))];

        float Ax = Zk.x + Zc.x, Ay = Zk.y - Zc.y;
        float Bx = Zk.x - Zc.x, By = Zk.y + Zc.y;

        float sn, cs;
        __sincosf(-3.14159265358979323846f * (float)k / (float)N2, &sn, &cs);
        float t1 = cs * By + sn * Bx;
        float t2 = cs * Bx - sn * By;

        float X0x = Ax + t1, X0y = Ay - t2;
        float X1x = Ax - t1, X1y = -(Ay + t2);

        float i0 = rsqrtf(X0x * X0x + X0y * X0y + 1e-24f);
        float i1 = rsqrtf(X1x * X1x + X1y * X1y + 1e-24f);
        w[k]      = make_float2(X0x * i0, X0y * i0);
        w[N2 - k] = make_float2(X1x * i1, X1y * i1);
    }

    if (tid == 0) pdl_trigger();
}

// ===========================================================================
// 4096-pt radix-4 DIF inverse FFT: single W^1 table (1024 entries);
// stage st indexes entry k*4^st; W^2, W^3 via cmul in-loop.
// ===========================================================================
__device__ __forceinline__ void gen_twiddles(float2* tw, int tid)
{
    for (int k = tid; k < NTW; k += FFT_THREADS) {
        float th = -3.14159265358979323846f * (float)k / 2048.0f;  // Q=1024 base
        float s1, c1;
        __sincosf(th, &s1, &c1);
        tw[k] = make_float2(c1, s1);
    }
}

__device__ __forceinline__ void ifft4096_dif(float2* s, const float2* tw, int tid)
{
    #pragma unroll
    for (int st = 0; st < 4; ++st) {
        const int lg = 10 - 2 * st;
        const int Q  = 1 << lg;
        #pragma unroll
        for (int u = 0; u < 2; ++u) {
            int j    = tid + u * FFT_THREADS;
            int k    = j & (Q - 1);
            int base = ((j >> lg) << (lg + 2)) + k;

            float2 a0 = s[SP(base)];
            float2 a1 = s[SP(base + Q)];
            float2 a2 = s[SP(base + 2 * Q)];
            float2 a3 = s[SP(base + 3 * Q)];

            float2 A = make_float2(a0.x + a2.x, a0.y + a2.y);
            float2 B = make_float2(a0.x - a2.x, a0.y - a2.y);
            float2 C = make_float2(a1.x + a3.x, a1.y + a3.y);
            float2 D = make_float2(a1.x - a3.x, a1.y - a3.y);

            float2 y0 = make_float2(A.x + C.x, A.y + C.y);
            float2 y1 = make_float2(B.x - D.y, B.y + D.x);
            float2 y2 = make_float2(A.x - C.x, A.y - C.y);
            float2 y3 = make_float2(B.x + D.y, B.y - D.x);

            // inverse twiddle: conj of base entry k*4^st; W^2, W^3 by cmul
            float2 w1 = tw[k << (2 * st)];
            w1.y = -w1.y;
            float2 w2 = cmul(w1, w1);
            float2 w3 = cmul(w2, w1);

            s[SP(base)]         = y0;
            s[SP(base + Q)]     = cmul(y1, w1);
            s[SP(base + 2 * Q)] = cmul(y2, w2);
            s[SP(base + 3 * Q)] = cmul(y3, w3);
        }
        __syncthreads();
    }

    if (tid < 256) {
        const float CS[10] = { 1.f,  0.92387953f,  0.70710678f,  0.38268343f,  0.f,
                              -0.38268343f, -0.70710678f, -0.92387953f, -1.f, -0.92387953f};
        const float SN[10] = { 0.f, -0.38268343f, -0.70710678f, -0.92387953f, -1.f,
                              -0.92387953f, -0.70710678f, -0.38268343f,  0.f,  0.38268343f};
        const float sg = -1.0f;
        float2 v[16];
        const int e0 = 16 * tid;
        #pragma unroll
        for (int m = 0; m < 16; ++m) v[m] = s[SP(e0 + m)];

        #pragma unroll
        for (int m = 0; m < 4; ++m) {
            float2 p = v[m], q = v[m + 4], r = v[m + 8], w = v[m + 12];
            float2 A = make_float2(p.x + r.x, p.y + r.y);
            float2 B = make_float2(p.x - r.x, p.y - r.y);
            float2 C = make_float2(q.x + w.x, q.y + w.y);
            float2 D = make_float2(q.x - w.x, q.y - w.y);
            float2 y0 = make_float2(A.x + C.x, A.y + C.y);
            float2 y1 = make_float2(B.x + sg * D.y, B.y - sg * D.x);
            float2 y2 = make_float2(A.x - C.x, A.y - C.y);
            float2 y3 = make_float2(B.x - sg * D.y, B.y + sg * D.x);
            float2 w1 = make_float2(CS[m],     sg * SN[m]);
            float2 w2 = make_float2(CS[2 * m], sg * SN[2 * m]);
            float2 w3 = make_float2(CS[3 * m], sg * SN[3 * m]);
            v[m]      = y0;
            v[m + 4]  = cmul(y1, w1);
            v[m + 8]  = cmul(y2, w2);
            v[m + 12] = cmul(y3, w3);
        }
        #pragma unroll
        for (int h = 0; h < 4; ++h) {
            float2 p = v[4*h], q = v[4*h+1], r = v[4*h+2], w = v[4*h+3];
            float2 A = make_float2(p.x + r.x, p.y + r.y);
            float2 B = make_float2(p.x - r.x, p.y - r.y);
            float2 C = make_float2(q.x + w.x, q.y + w.y);
            float2 D = make_float2(q.x - w.x, q.y - w.y);
            v[4*h]   = make_float2(A.x + C.x, A.y + C.y);
            v[4*h+1] = make_float2(B.x + sg * D.y, B.y - sg * D.x);
            v[4*h+2] = make_float2(A.x - C.x, A.y - C.y);
            v[4*h+3] = make_float2(B.x - sg * D.y, B.y + sg * D.x);
        }
        #pragma unroll
        for (int m = 0; m < 16; ++m) s[SP(e0 + m)] = v[m];
    }
    __syncthreads();
}

// ===========================================================================
// Kernel 2: cross-spectrum + inverse FFT, two pairs per iFFT.
// 224 blocks x 512 threads, smem 43.1 KB (co-resident blocks). PDL both sides.
// ===========================================================================
__global__ void __launch_bounds__(FFT_THREADS) k_xcorr(const int* __restrict__ comb)
{
    extern __shared__ float2 dyn[];
    float2* s  = dyn;
    float2* tw = dyn + SMEM_PAD;

    const int tid = threadIdx.x;
    if (blockIdx.x == 0 && tid == 0) {
        g_done = 0;
        #pragma unroll
        for (int b = 0; b < BATCH; ++b) g_best[b] = 0ull;
    }

    const int q0 = blockIdx.x * 2, q1 = q0 + 1;
    const int b0 = q0 / NPAIR, p0 = q0 % NPAIR;
    const int b1 = q1 / NPAIR, p1 = q1 % NPAIR;

    const int ia0 = comb[2 * p0], ib0 = comb[2 * p0 + 1];
    const int ia1 = comb[2 * p1], ib1 = comb[2 * p1 + 1];

    gen_twiddles(tw, tid);          // overlaps with whiten via PDL

    pdl_wait();                     // g_W must be complete beyond here

    const float2* Wa0 = g_W + (size_t)(b0 * NMICS + ia0) * NBINS;
    const float2* Wb0 = g_W + (size_t)(b0 * NMICS + ib0) * NBINS;
    const float2* Wa1 = g_W + (size_t)(b1 * NMICS + ia1) * NBINS;
    const float2* Wb1 = g_W + (size_t)(b1 * NMICS + ib1) * NBINS;

    for (int k = tid; k <= N_FFT / 2; k += FFT_THREADS) {
        float2 a0 = Wa0[k], c0 = Wb0[k];
        float x1r = a0.x * c0.x + a0.y * c0.y;
        float x1i = a0.y * c0.x - a0.x * c0.y;
        float2 a1 = Wa1[k], c1 = Wb1[k];
        float x2r = a1.x * c1.x + a1.y * c1.y;
        float x2i = a1.y * c1.x - a1.x * c1.y;

        s[SP(k)] = make_float2(x1r - x2i, x1i + x2r);
        if (k > 0 && k < N_FFT / 2)
            s[SP(N_FFT - k)] = make_float2(x1r + x2i, x2r - x1i);
    }
    __syncthreads();

    ifft4096_dif(s, tw, tid);

    if (tid < NLAG) {
        int idx = (tid + (N_FFT - 40)) & (N_FFT - 1);
        float2 v = s[SP(dr12(idx))];
        g_cc[(p0 * NLAG + tid) * BATCH + b0] = v.x;
        g_cc[(p1 * NLAG + tid) * BATCH + b1] = v.y;
    }

    if (tid == 0) pdl_trigger();
}

// ===========================================================================
// Kernel 3: SRP accumulation + argmax + fused final decode. (proven)
// ===========================================================================
__device__ __forceinline__ unsigned int fkey(float f)
{
    unsigned int b = __float_as_uint(f);
    return (b & 0x80000000u) ? ~b : (b | 0x80000000u);
}

__global__ void __launch_bounds__(256) k_srp(const int* __restrict__ tau, int G,
                                             const float* __restrict__ grid_x,
                                             const float* __restrict__ cen,
                                             float* __restrict__ out)
{
    __shared__ unsigned long long sbest[BATCH];
    __shared__ int s_last;
    const int tid = threadIdx.x;
    if (tid < BATCH) sbest[tid] = 0ull;
    if (tid == 0) s_last = 0;
    __syncthreads();

    pdl_wait();                     // g_cc (and g_best reset) complete beyond here

    const int tIdx = blockIdx.x * 256 + tid;
    const int g    = tIdx >> 3;
    const int bp   = tid & 7;

    unsigned long long k0 = 0ull, k1 = 0ull;

    if (g < G) {
        float2 pw = make_float2(0.0f, 0.0f);
        const int4* trow = (const int4*)(tau + (size_t)g * NPAIR);
        #pragma unroll
        for (int pc = 0; pc < NPAIR / 4; ++pc) {
            int4 tv = trow[pc];
            int ts[4] = { tv.x, tv.y, tv.z, tv.w };
            #pragma unroll
            for (int e = 0; e < 4; ++e) {
                int p = pc * 4 + e;
                float2 r = *(const float2*)(g_cc + (p * NLAG + ts[e]) * BATCH + bp * 2);
                pw.x += r.x; pw.y += r.y;
            }
        }
        const unsigned int gk = ~(unsigned int)g;
        k0 = ((unsigned long long)fkey(pw.x) << 32) | gk;
        k1 = ((unsigned long long)fkey(pw.y) << 32) | gk;
    }

    #pragma unroll
    for (int off = 8; off < 32; off <<= 1) {
        unsigned long long o0 = __shfl_xor_sync(0xFFFFFFFFu, k0, off);
        unsigned long long o1 = __shfl_xor_sync(0xFFFFFFFFu, k1, off);
        if (o0 > k0) k0 = o0;
        if (o1 > k1) k1 = o1;
    }
    if ((tid & 31) < 8) {
        atomicMax(&sbest[bp * 2],     k0);
        atomicMax(&sbest[bp * 2 + 1], k1);
    }
    __syncthreads();

    if (tid < BATCH) {
        atomicMax(&g_best[tid], sbest[tid]);
        __threadfence();
    }
    __syncthreads();
    if (tid == 0) {
        int ticket = atomicAdd(&g_done, 1);
        if (ticket == (int)gridDim.x - 1) { __threadfence(); s_last = 1; }
    }
    __syncthreads();
    if (s_last && tid < BATCH) {
        unsigned long long v = atomicMax(&g_best[tid], 0ull);
        unsigned int idx = ~(unsigned int)(v & 0xFFFFFFFFull);
        #pragma unroll
        for (int j = 0; j < 3; ++j)
            out[tid * 3 + j] = grid_x[(size_t)idx * 3 + j] - cen[j];
    }
}

// ---------------------------------------------------------------------------
extern "C" void kernel_launch(void* const* d_in, const int* in_sizes, int n_in,
                              void* d_out, int out_size)
{
    const float* signal = (const float*)d_in[0];
    const float* grid_x = (const float*)d_in[1];
    const int*   tau    = (const int*)d_in[2];
    const int*   comb   = (const int*)d_in[3];
    const float* cen    = (const float*)d_in[4];

    const int G = in_sizes[1] / 3;

    cudaFuncSetAttribute(k_xcorr, cudaFuncAttributeMaxDynamicSharedMemorySize,
                         (int)XC_SMEM);

    // primary: normal launch (split whiten: 256 blocks x 256 threads)
    k_fft_whiten<<<BATCH * NMICS * 2, WH_THREADS, WH_SMEM>>>(signal);

    // dependents: PDL — prologue overlaps primary; wait gates the data reads.
    cudaLaunchAttribute attr[1];
    attr[0].id = cudaLaunchAttributeProgrammaticStreamSerialization;
    attr[0].val.programmaticStreamSerializationAllowed = 1;

    {
        cudaLaunchConfig_t cfg = {};
        cfg.gridDim  = dim3(BATCH * NPAIR / 2, 1, 1);
        cfg.blockDim = dim3(FFT_THREADS, 1, 1);
        cfg.dynamicSmemBytes = XC_SMEM;
        cfg.stream = 0;
        cfg.attrs = attr;
        cfg.numAttrs = 1;
        cudaLaunchKernelEx(&cfg, k_xcorr, comb);
    }
    {
        cudaLaunchConfig_t cfg = {};
        cfg.gridDim  = dim3((8 * G + 255) / 256, 1, 1);
        cfg.blockDim = dim3(256, 1, 1);
        cfg.dynamicSmemBytes = 0;
        cfg.stream = 0;
        cfg.attrs = attr;
        cfg.numAttrs = 1;
        cudaLaunchKernelEx(&cfg, k_srp, tau, G, grid_x, cen, (float*)d_out);
    }
}

// round 16
// speedup vs baseline: 1.0529x; 1.0300x over previous
#include <cuda_runtime.h>
#include <stdint.h>

#define N_FFT  4096
#define NBINS  2049
#define NMICS  8
#define BATCH  16
#define NPAIR  28
#define NLAG   81
#define FFT_THREADS 512      // xcorr
#define WH_THREADS  256      // whiten (split kernel)

// padded smem index: conflict-free / near-conflict-free for patterns used
#define SP(i) ((i) + ((i) >> 4) + ((i) >> 8))

// ----- 4096-pt iFFT (xcorr) constants -----
#define SMEM_PAD   4368
#define NTW        1024
#define XC_SMEM    ((SMEM_PAD + NTW) * sizeof(float2))        // ~43.1 KB

// ----- split whiten constants -----
#define N2         2048
#define WPAD       1104
#define NTWW       168
#define WH_SMEM    ((WPAD + 3 * NTWW) * sizeof(float2))       // ~12.9 KB

__device__ float2 g_W[BATCH * NMICS * NBINS];        // whitened spectra (natural order)
__device__ float  g_cc[NPAIR * NLAG * BATCH];        // cc table [p][t][b16]
__device__ unsigned long long g_best[BATCH];
__device__ int    g_done;

// PDL primitives
__device__ __forceinline__ void pdl_wait()    { asm volatile("griddepcontrol.wait;" ::: "memory"); }
__device__ __forceinline__ void pdl_trigger() { asm volatile("griddepcontrol.launch_dependents;" ::: "memory"); }

// base-4 digit reversal of 12-bit index (involution) — 4096 iFFT output perm
__device__ __forceinline__ int dr12(int i)
{
    unsigned x = __brev((unsigned)i) >> 20;
    return (int)(((x & 0xAAAu) >> 1) | ((x & 0x555u) << 1));
}

// DIF output position within a 512-pt sub-chain (stages Q=128,32,8 + 8-pt tail)
__device__ __forceinline__ int perm512(int t)
{
    return ((t & 3) << 7) | (((t >> 2) & 3) << 5) | (((t >> 4) & 3) << 3)
         | (((t >> 6) & 3) << 1) | (t >> 8);
}

__device__ __forceinline__ float2 cmul(float2 a, float2 b)
{
    return make_float2(a.x * b.x - a.y * b.y, a.x * b.y + a.y * b.x);
}

// ===========================================================================
// Kernel 1 (SPLIT): forward real-4096 FFT via 2048-pt complex FFT, TWO CTAs
// per signal (round-13/14, proven). 256 blocks x 256 threads.
// ===========================================================================
__global__ void __launch_bounds__(WH_THREADS) k_fft_whiten(const float* __restrict__ sig)
{
    extern __shared__ float2 dyn[];
    float2* s  = dyn;                 // 1024 padded (2 subs x 512)
    float2* tw = dyn + WPAD;          // 3 * NTWW

    const int tid  = threadIdx.x;
    const int sgn  = blockIdx.x >> 1;
    const int half = blockIdx.x & 1;

    if (tid < NTWW) {
        int Q, k;
        if      (tid < 128) { Q = 128; k = tid; }
        else if (tid < 160) { Q = 32;  k = tid - 128; }
        else                { Q = 8;   k = tid - 160; }
        float th = -3.14159265358979323846f * (float)k / (2.0f * (float)Q);
        float s1, c1, s2, c2, s3, c3;
        __sincosf(th,        &s1, &c1);
        __sincosf(th * 2.0f, &s2, &c2);
        __sincosf(th * 3.0f, &s3, &c3);
        tw[tid]            = make_float2(c1, s1);
        tw[tid + NTWW]     = make_float2(c2, s2);
        tw[tid + 2 * NTWW] = make_float2(c3, s3);
    }

    const float2* xz = (const float2*)(sig + (size_t)sgn * N_FFT);
    #pragma unroll
    for (int u = 0; u < 2; ++u) {
        int j = tid + u * WH_THREADS;
        float2 a0 = xz[j];
        float2 a1 = xz[j + 512];
        float2 a2 = xz[j + 1024];
        float2 a3 = xz[j + 1536];

        float2 A = make_float2(a0.x + a2.x, a0.y + a2.y);
        float2 B = make_float2(a0.x - a2.x, a0.y - a2.y);
        float2 C = make_float2(a1.x + a3.x, a1.y + a3.y);
        float2 D = make_float2(a1.x - a3.x, a1.y - a3.y);

        float th = -6.283185307179586f * (float)j / 2048.0f;
        if (half == 0) {
            float sn, cs;
            __sincosf(th * 2.0f, &sn, &cs);
            s[SP(j)]       = make_float2(A.x + C.x, A.y + C.y);
            s[SP(512 + j)] = cmul(make_float2(A.x - C.x, A.y - C.y),
                                  make_float2(cs, sn));
        } else {
            float sn, cs;
            __sincosf(th, &sn, &cs);
            float2 w1 = make_float2(cs, sn);
            float2 w2 = cmul(w1, w1);
            float2 w3 = cmul(w2, w1);
            s[SP(j)]       = cmul(make_float2(B.x + D.y, B.y - D.x), w1);
            s[SP(512 + j)] = cmul(make_float2(B.x - D.y, B.y + D.x), w3);
        }
    }
    __syncthreads();

    const int OFF[3] = {0, 128, 160};
    #pragma unroll
    for (int st = 0; st < 3; ++st) {
        const int lg = 7 - 2 * st;
        const int Q  = 1 << lg;
        int sub = tid >> 7;
        int j   = tid & 127;
        int k   = j & (Q - 1);
        int base = sub * 512 + ((j >> lg) << (lg + 2)) + k;

        float2 a0 = s[SP(base)];
        float2 a1 = s[SP(base + Q)];
        float2 a2 = s[SP(base + 2 * Q)];
        float2 a3 = s[SP(base + 3 * Q)];

        float2 A = make_float2(a0.x + a2.x, a0.y + a2.y);
        float2 B = make_float2(a0.x - a2.x, a0.y - a2.y);
        float2 C = make_float2(a1.x + a3.x, a1.y + a3.y);
        float2 D = make_float2(a1.x - a3.x, a1.y - a3.y);

        float2 y0 = make_float2(A.x + C.x, A.y + C.y);
        float2 y1 = make_float2(B.x + D.y, B.y - D.x);
        float2 y2 = make_float2(A.x - C.x, A.y - C.y);
        float2 y3 = make_float2(B.x - D.y, B.y + D.x);

        int ti = OFF[st] + k;
        s[SP(base)]         = y0;
        s[SP(base + Q)]     = cmul(y1, tw[ti]);
        s[SP(base + 2 * Q)] = cmul(y2, tw[ti + NTWW]);
        s[SP(base + 3 * Q)] = cmul(y3, tw[ti + 2 * NTWW]);
        __syncthreads();
    }

    if (tid < 128) {
        const float RT = 0.70710678118654752f;
        float2 v[8];
        const int e0 = tid * 8;
        #pragma unroll
        for (int i = 0; i < 8; ++i) v[i] = s[SP(e0 + i)];

        {
            float2 A = make_float2(v[0].x + v[4].x, v[0].y + v[4].y);
            float2 B = make_float2(v[0].x - v[4].x, v[0].y - v[4].y);
            float2 C = make_float2(v[2].x + v[6].x, v[2].y + v[6].y);
            float2 D = make_float2(v[2].x - v[6].x, v[2].y - v[6].y);
            v[0] = make_float2(A.x + C.x, A.y + C.y);
            v[2] = make_float2(B.x + D.y, B.y - D.x);
            v[4] = make_float2(A.x - C.x, A.y - C.y);
            v[6] = make_float2(B.x - D.y, B.y + D.x);
        }
        {
            float2 A = make_float2(v[1].x + v[5].x, v[1].y + v[5].y);
            float2 B = make_float2(v[1].x - v[5].x, v[1].y - v[5].y);
            float2 C = make_float2(v[3].x + v[7].x, v[3].y + v[7].y);
            float2 D = make_float2(v[3].x - v[7].x, v[3].y - v[7].y);
            float2 y1 = make_float2(B.x + D.y, B.y - D.x);
            float2 y2 = make_float2(A.x - C.x, A.y - C.y);
            float2 y3 = make_float2(B.x - D.y, B.y + D.x);
            v[1] = make_float2(A.x + C.x, A.y + C.y);
            v[3] = make_float2((y1.x + y1.y) * RT, (y1.y - y1.x) * RT);
            v[5] = make_float2(y2.y, -y2.x);
            v[7] = make_float2((y3.y - y3.x) * RT, -(y3.x + y3.y) * RT);
        }
        #pragma unroll
        for (int i = 0; i < 4; ++i) {
            float2 a = v[2 * i], b = v[2 * i + 1];
            v[2 * i]     = make_float2(a.x + b.x, a.y + b.y);
            v[2 * i + 1] = make_float2(a.x - b.x, a.y - b.y);
        }
        #pragma unroll
        for (int i = 0; i < 8; ++i) s[SP(e0 + i)] = v[i];
    }
    __syncthreads();

    float2* w = g_W + (size_t)sgn * NBINS;
    for (int k = 2 * tid + half; k <= N2 / 2; k += 2 * WH_THREADS) {
        int m  = k;
        int mc = (N2 - k) & (N2 - 1);
        float2 Zk = s[SP(((m  & 3) >> 1) * 512 + perm512(m  >> 2))];
        float2 Zc = s[SP(((mc & 3) >> 1) * 512 + perm512(mc >> 2))];

        float Ax = Zk.x + Zc.x, Ay = Zk.y - Zc.y;
        float Bx = Zk.x - Zc.x, By = Zk.y + Zc.y;

        float sn, cs;
        __sincosf(-3.14159265358979323846f * (float)k / (float)N2, &sn, &cs);
        float t1 = cs * By + sn * Bx;
        float t2 = cs * Bx - sn * By;

        float X0x = Ax + t1, X0y = Ay - t2;
        float X1x = Ax - t1, X1y = -(Ay + t2);

        float i0 = rsqrtf(X0x * X0x + X0y * X0y + 1e-24f);
        float i1 = rsqrtf(X1x * X1x + X1y * X1y + 1e-24f);
        w[k]      = make_float2(X0x * i0, X0y * i0);
        w[N2 - k] = make_float2(X1x * i1, X1y * i1);
    }

    if (tid == 0) pdl_trigger();
}

// ===========================================================================
// 4096-pt radix-4 DIF inverse FFT: single W^1 table; W^2,W^3 via cmul. (r14)
// ===========================================================================
__device__ __forceinline__ void gen_twiddles(float2* tw, int tid)
{
    for (int k = tid; k < NTW; k += FFT_THREADS) {
        float th = -3.14159265358979323846f * (float)k / 2048.0f;
        float s1, c1;
        __sincosf(th, &s1, &c1);
        tw[k] = make_float2(c1, s1);
    }
}

__device__ __forceinline__ void ifft4096_dif(float2* s, const float2* tw, int tid)
{
    #pragma unroll
    for (int st = 0; st < 4; ++st) {
        const int lg = 10 - 2 * st;
        const int Q  = 1 << lg;
        #pragma unroll
        for (int u = 0; u < 2; ++u) {
            int j    = tid + u * FFT_THREADS;
            int k    = j & (Q - 1);
            int base = ((j >> lg) << (lg + 2)) + k;

            float2 a0 = s[SP(base)];
            float2 a1 = s[SP(base + Q)];
            float2 a2 = s[SP(base + 2 * Q)];
            float2 a3 = s[SP(base + 3 * Q)];

            float2 A = make_float2(a0.x + a2.x, a0.y + a2.y);
            float2 B = make_float2(a0.x - a2.x, a0.y - a2.y);
            float2 C = make_float2(a1.x + a3.x, a1.y + a3.y);
            float2 D = make_float2(a1.x - a3.x, a1.y - a3.y);

            float2 y0 = make_float2(A.x + C.x, A.y + C.y);
            float2 y1 = make_float2(B.x - D.y, B.y + D.x);
            float2 y2 = make_float2(A.x - C.x, A.y - C.y);
            float2 y3 = make_float2(B.x + D.y, B.y - D.x);

            float2 w1 = tw[k << (2 * st)];
            w1.y = -w1.y;
            float2 w2 = cmul(w1, w1);
            float2 w3 = cmul(w2, w1);

            s[SP(base)]         = y0;
            s[SP(base + Q)]     = cmul(y1, w1);
            s[SP(base + 2 * Q)] = cmul(y2, w2);
            s[SP(base + 3 * Q)] = cmul(y3, w3);
        }
        __syncthreads();
    }

    if (tid < 256) {
        const float CS[10] = { 1.f,  0.92387953f,  0.70710678f,  0.38268343f,  0.f,
                              -0.38268343f, -0.70710678f, -0.92387953f, -1.f, -0.92387953f};
        const float SN[10] = { 0.f, -0.38268343f, -0.70710678f, -0.92387953f, -1.f,
                              -0.92387953f, -0.70710678f, -0.38268343f,  0.f,  0.38268343f};
        const float sg = -1.0f;
        float2 v[16];
        const int e0 = 16 * tid;
        #pragma unroll
        for (int m = 0; m < 16; ++m) v[m] = s[SP(e0 + m)];

        #pragma unroll
        for (int m = 0; m < 4; ++m) {
            float2 p = v[m], q = v[m + 4], r = v[m + 8], w = v[m + 12];
            float2 A = make_float2(p.x + r.x, p.y + r.y);
            float2 B = make_float2(p.x - r.x, p.y - r.y);
            float2 C = make_float2(q.x + w.x, q.y + w.y);
            float2 D = make_float2(q.x - w.x, q.y - w.y);
            float2 y0 = make_float2(A.x + C.x, A.y + C.y);
            float2 y1 = make_float2(B.x + sg * D.y, B.y - sg * D.x);
            float2 y2 = make_float2(A.x - C.x, A.y - C.y);
            float2 y3 = make_float2(B.x - sg * D.y, B.y + sg * D.x);
            float2 w1 = make_float2(CS[m],     sg * SN[m]);
            float2 w2 = make_float2(CS[2 * m], sg * SN[2 * m]);
            float2 w3 = make_float2(CS[3 * m], sg * SN[3 * m]);
            v[m]      = y0;
            v[m + 4]  = cmul(y1, w1);
            v[m + 8]  = cmul(y2, w2);
            v[m + 12] = cmul(y3, w3);
        }
        #pragma unroll
        for (int h = 0; h < 4; ++h) {
            float2 p = v[4*h], q = v[4*h+1], r = v[4*h+2], w = v[4*h+3];
            float2 A = make_float2(p.x + r.x, p.y + r.y);
            float2 B = make_float2(p.x - r.x, p.y - r.y);
            float2 C = make_float2(q.x + w.x, q.y + w.y);
            float2 D = make_float2(q.x - w.x, q.y - w.y);
            v[4*h]   = make_float2(A.x + C.x, A.y + C.y);
            v[4*h+1] = make_float2(B.x + sg * D.y, B.y - sg * D.x);
            v[4*h+2] = make_float2(A.x - C.x, A.y - C.y);
            v[4*h+3] = make_float2(B.x - sg * D.y, B.y + sg * D.x);
        }
        #pragma unroll
        for (int m = 0; m < 16; ++m) s[SP(e0 + m)] = v[m];
    }
    __syncthreads();
}

// ===========================================================================
// Kernel 2: cross-spectrum + inverse FFT, two pairs per iFFT. (r14, proven)
// ===========================================================================
__global__ void __launch_bounds__(FFT_THREADS) k_xcorr(const int* __restrict__ comb)
{
    extern __shared__ float2 dyn[];
    float2* s  = dyn;
    float2* tw = dyn + SMEM_PAD;

    const int tid = threadIdx.x;
    if (blockIdx.x == 0 && tid == 0) {
        g_done = 0;
        #pragma unroll
        for (int b = 0; b < BATCH; ++b) g_best[b] = 0ull;
    }

    const int q0 = blockIdx.x * 2, q1 = q0 + 1;
    const int b0 = q0 / NPAIR, p0 = q0 % NPAIR;
    const int b1 = q1 / NPAIR, p1 = q1 % NPAIR;

    const int ia0 = comb[2 * p0], ib0 = comb[2 * p0 + 1];
    const int ia1 = comb[2 * p1], ib1 = comb[2 * p1 + 1];

    gen_twiddles(tw, tid);          // overlaps with whiten via PDL

    pdl_wait();

    const float2* Wa0 = g_W + (size_t)(b0 * NMICS + ia0) * NBINS;
    const float2* Wb0 = g_W + (size_t)(b0 * NMICS + ib0) * NBINS;
    const float2* Wa1 = g_W + (size_t)(b1 * NMICS + ia1) * NBINS;
    const float2* Wb1 = g_W + (size_t)(b1 * NMICS + ib1) * NBINS;

    for (int k = tid; k <= N_FFT / 2; k += FFT_THREADS) {
        float2 a0 = Wa0[k], c0 = Wb0[k];
        float x1r = a0.x * c0.x + a0.y * c0.y;
        float x1i = a0.y * c0.x - a0.x * c0.y;
        float2 a1 = Wa1[k], c1 = Wb1[k];
        float x2r = a1.x * c1.x + a1.y * c1.y;
        float x2i = a1.y * c1.x - a1.x * c1.y;

        s[SP(k)] = make_float2(x1r - x2i, x1i + x2r);
        if (k > 0 && k < N_FFT / 2)
            s[SP(N_FFT - k)] = make_float2(x1r + x2i, x2r - x1i);
    }
    __syncthreads();

    ifft4096_dif(s, tw, tid);

    if (tid < NLAG) {
        int idx = (tid + (N_FFT - 40)) & (N_FFT - 1);
        float2 v = s[SP(dr12(idx))];
        g_cc[(p0 * NLAG + tid) * BATCH + b0] = v.x;
        g_cc[(p1 * NLAG + tid) * BATCH + b1] = v.y;
    }

    if (tid == 0) pdl_trigger();
}

// ===========================================================================
// Kernel 3: SRP accumulation + argmax + fused final decode.
// tau rows prefetched into 16B-ALIGNED smem BEFORE pdl_wait (fix for r15's
// misaligned int4 store: __shared__ int was only 4B-aligned).
// ===========================================================================
__device__ __forceinline__ unsigned int fkey(float f)
{
    unsigned int b = __float_as_uint(f);
    return (b & 0x80000000u) ? ~b : (b | 0x80000000u);
}

__global__ void __launch_bounds__(256) k_srp(const int* __restrict__ tau, int G,
                                             const float* __restrict__ grid_x,
                                             const float* __restrict__ cen,
                                             float* __restrict__ out)
{
    __shared__ unsigned long long sbest[BATCH];
    __shared__ int s_last;
    __shared__ __align__(16) int s_tau[32 * NPAIR];   // 32 pts x 28 taus, 16B-aligned

    const int tid = threadIdx.x;
    if (tid < BATCH) sbest[tid] = 0ull;
    if (tid == 0) s_last = 0;

    const int g0 = blockIdx.x * 32;          // first grid point of this block

    // prefetch tau (independent of xcorr) — issues before the PDL wait
    if (tid < 32 * (NPAIR / 4)) {            // 224 threads: row = tid/7, q = tid%7
        int row = tid / 7;
        int q   = tid - row * 7;
        int g   = g0 + row;
        if (g < G) {
            int4 v = ((const int4*)(tau + (size_t)g * NPAIR))[q];
            *(int4*)(s_tau + row * NPAIR + q * 4) = v;
        }
    }

    pdl_wait();                              // g_cc ready beyond here
    __syncthreads();                         // s_tau ready

    const int lg = tid >> 3;                 // local grid point 0..31
    const int g  = g0 + lg;
    const int bp = tid & 7;                  // batches 2bp, 2bp+1

    unsigned long long k0 = 0ull, k1 = 0ull;

    if (g < G) {
        float2 pw = make_float2(0.0f, 0.0f);
        const int* trow = s_tau + lg * NPAIR;
        #pragma unroll
        for (int p = 0; p < NPAIR; ++p) {
            float2 r = *(const float2*)(g_cc + (p * NLAG + trow[p]) * BATCH + bp * 2);
            pw.x += r.x; pw.y += r.y;
        }
        const unsigned int gk = ~(unsigned int)g;
        k0 = ((unsigned long long)fkey(pw.x) << 32) | gk;
        k1 = ((unsigned long long)fkey(pw.y) << 32) | gk;
    }

    #pragma unroll
    for (int off = 8; off < 32; off <<= 1) {
        unsigned long long o0 = __shfl_xor_sync(0xFFFFFFFFu, k0, off);
        unsigned long long o1 = __shfl_xor_sync(0xFFFFFFFFu, k1, off);
        if (o0 > k0) k0 = o0;
        if (o1 > k1) k1 = o1;
    }
    if ((tid & 31) < 8) {
        atomicMax(&sbest[bp * 2],     k0);
        atomicMax(&sbest[bp * 2 + 1], k1);
    }
    __syncthreads();

    if (tid < BATCH) {
        atomicMax(&g_best[tid], sbest[tid]);
        __threadfence();
    }
    __syncthreads();
    if (tid == 0) {
        int ticket = atomicAdd(&g_done, 1);
        if (ticket == (int)gridDim.x - 1) { __threadfence(); s_last = 1; }
    }
    __syncthreads();
    if (s_last && tid < BATCH) {
        unsigned long long v = atomicMax(&g_best[tid], 0ull);
        unsigned int idx = ~(unsigned int)(v & 0xFFFFFFFFull);
        #pragma unroll
        for (int j = 0; j < 3; ++j)
            out[tid * 3 + j] = grid_x[(size_t)idx * 3 + j] - cen[j];
    }
}

// ---------------------------------------------------------------------------
extern "C" void kernel_launch(void* const* d_in, const int* in_sizes, int n_in,
                              void* d_out, int out_size)
{
    const float* signal = (const float*)d_in[0];
    const float* grid_x = (const float*)d_in[1];
    const int*   tau    = (const int*)d_in[2];
    const int*   comb   = (const int*)d_in[3];
    const float* cen    = (const float*)d_in[4];

    const int G = in_sizes[1] / 3;

    cudaFuncSetAttribute(k_xcorr, cudaFuncAttributeMaxDynamicSharedMemorySize,
                         (int)XC_SMEM);

    // primary: split whiten (256 blocks x 256 threads)
    k_fft_whiten<<<BATCH * NMICS * 2, WH_THREADS, WH_SMEM>>>(signal);

    // dependents: PDL — prologue overlaps primary; wait gates the data reads.
    cudaLaunchAttribute attr[1];
    attr[0].id = cudaLaunchAttributeProgrammaticStreamSerialization;
    attr[0].val.programmaticStreamSerializationAllowed = 1;

    {
        cudaLaunchConfig_t cfg = {};
        cfg.gridDim  = dim3(BATCH * NPAIR / 2, 1, 1);
        cfg.blockDim = dim3(FFT_THREADS, 1, 1);
        cfg.dynamicSmemBytes = XC_SMEM;
        cfg.stream = 0;
        cfg.attrs = attr;
        cfg.numAttrs = 1;
        cudaLaunchKernelEx(&cfg, k_xcorr, comb);
    }
    {
        cudaLaunchConfig_t cfg = {};
        cfg.gridDim  = dim3((8 * G + 255) / 256, 1, 1);
        cfg.blockDim = dim3(256, 1, 1);
        cfg.dynamicSmemBytes = 0;
        cfg.stream = 0;
        cfg.attrs = attr;
        cfg.numAttrs = 1;
        cudaLaunchKernelEx(&cfg, k_srp, tau, G, grid_x, cen, (float*)d_out);
    }
}

// round 17
// speedup vs baseline: 1.1068x; 1.0511x over previous
#include <cuda_runtime.h>
#include <stdint.h>

#define N_FFT  4096
#define NBINS  2049
#define NMICS  8
#define BATCH  16
#define NPAIR  28
#define NLAG   81
#define FFT_THREADS 512      // xcorr
#define WH_THREADS  256      // whiten (split kernel)
#define SRP_THREADS 512      // srp (64 grid points / block)

// padded smem index: conflict-free / near-conflict-free for patterns used
#define SP(i) ((i) + ((i) >> 4) + ((i) >> 8))

// ----- 4096-pt iFFT (xcorr) constants -----
#define SMEM_PAD   4368
#define NTW        1024
#define XC_SMEM    ((SMEM_PAD + NTW) * sizeof(float2))        // ~43.1 KB

// ----- split whiten constants -----
#define N2         2048
#define WPAD       1104
#define NTWW       168
#define WH_SMEM    ((WPAD + 3 * NTWW) * sizeof(float2))       // ~12.9 KB

__device__ float2 g_W[BATCH * NMICS * NBINS];        // whitened spectra (natural order)
__device__ float  g_cc[NPAIR * NLAG * BATCH];        // cc table [p][t][b16]
__device__ unsigned long long g_best[BATCH];
__device__ int    g_done;

// PDL primitives
__device__ __forceinline__ void pdl_wait()    { asm volatile("griddepcontrol.wait;" ::: "memory"); }
__device__ __forceinline__ void pdl_trigger() { asm volatile("griddepcontrol.launch_dependents;" ::: "memory"); }

// base-4 digit reversal of 12-bit index (involution) — 4096 iFFT output perm
__device__ __forceinline__ int dr12(int i)
{
    unsigned x = __brev((unsigned)i) >> 20;
    return (int)(((x & 0xAAAu) >> 1) | ((x & 0x555u) << 1));
}

// DIF output position within a 512-pt sub-chain (stages Q=128,32,8 + 8-pt tail)
__device__ __forceinline__ int perm512(int t)
{
    return ((t & 3) << 7) | (((t >> 2) & 3) << 5) | (((t >> 4) & 3) << 3)
         | (((t >> 6) & 3) << 1) | (t >> 8);
}

__device__ __forceinline__ float2 cmul(float2 a, float2 b)
{
    return make_float2(a.x * b.x - a.y * b.y, a.x * b.y + a.y * b.x);
}

// ===========================================================================
// Kernel 1 (SPLIT): forward real-4096 FFT via 2048-pt complex FFT, TWO CTAs
// per signal (round-13/14, proven). 256 blocks x 256 threads.
// ===========================================================================
__global__ void __launch_bounds__(WH_THREADS) k_fft_whiten(const float* __restrict__ sig)
{
    extern __shared__ float2 dyn[];
    float2* s  = dyn;                 // 1024 padded (2 subs x 512)
    float2* tw = dyn + WPAD;          // 3 * NTWW

    const int tid  = threadIdx.x;
    const int sgn  = blockIdx.x >> 1;
    const int half = blockIdx.x & 1;

    if (tid < NTWW) {
        int Q, k;
        if      (tid < 128) { Q = 128; k = tid; }
        else if (tid < 160) { Q = 32;  k = tid - 128; }
        else                { Q = 8;   k = tid - 160; }
        float th = -3.14159265358979323846f * (float)k / (2.0f * (float)Q);
        float s1, c1, s2, c2, s3, c3;
        __sincosf(th,        &s1, &c1);
        __sincosf(th * 2.0f, &s2, &c2);
        __sincosf(th * 3.0f, &s3, &c3);
        tw[tid]            = make_float2(c1, s1);
        tw[tid + NTWW]     = make_float2(c2, s2);
        tw[tid + 2 * NTWW] = make_float2(c3, s3);
    }

    const float2* xz = (const float2*)(sig + (size_t)sgn * N_FFT);
    #pragma unroll
    for (int u = 0; u < 2; ++u) {
        int j = tid + u * WH_THREADS;
        float2 a0 = xz[j];
        float2 a1 = xz[j + 512];
        float2 a2 = xz[j + 1024];
        float2 a3 = xz[j + 1536];

        float2 A = make_float2(a0.x + a2.x, a0.y + a2.y);
        float2 B = make_float2(a0.x - a2.x, a0.y - a2.y);
        float2 C = make_float2(a1.x + a3.x, a1.y + a3.y);
        float2 D = make_float2(a1.x - a3.x, a1.y - a3.y);

        float th = -6.283185307179586f * (float)j / 2048.0f;
        if (half == 0) {
            float sn, cs;
            __sincosf(th * 2.0f, &sn, &cs);
            s[SP(j)]       = make_float2(A.x + C.x, A.y + C.y);
            s[SP(512 + j)] = cmul(make_float2(A.x - C.x, A.y - C.y),
                                  make_float2(cs, sn));
        } else {
            float sn, cs;
            __sincosf(th, &sn, &cs);
            float2 w1 = make_float2(cs, sn);
            float2 w2 = cmul(w1, w1);
            float2 w3 = cmul(w2, w1);
            s[SP(j)]       = cmul(make_float2(B.x + D.y, B.y - D.x), w1);
            s[SP(512 + j)] = cmul(make_float2(B.x - D.y, B.y + D.x), w3);
        }
    }
    __syncthreads();

    const int OFF[3] = {0, 128, 160};
    #pragma unroll
    for (int st = 0; st < 3; ++st) {
        const int lg = 7 - 2 * st;
        const int Q  = 1 << lg;
        int sub = tid >> 7;
        int j   = tid & 127;
        int k   = j & (Q - 1);
        int base = sub * 512 + ((j >> lg) << (lg + 2)) + k;

        float2 a0 = s[SP(base)];
        float2 a1 = s[SP(base + Q)];
        float2 a2 = s[SP(base + 2 * Q)];
        float2 a3 = s[SP(base + 3 * Q)];

        float2 A = make_float2(a0.x + a2.x, a0.y + a2.y);
        float2 B = make_float2(a0.x - a2.x, a0.y - a2.y);
        float2 C = make_float2(a1.x + a3.x, a1.y + a3.y);
        float2 D = make_float2(a1.x - a3.x, a1.y - a3.y);

        float2 y0 = make_float2(A.x + C.x, A.y + C.y);
        float2 y1 = make_float2(B.x + D.y, B.y - D.x);
        float2 y2 = make_float2(A.x - C.x, A.y - C.y);
        float2 y3 = make_float2(B.x - D.y, B.y + D.x);

        int ti = OFF[st] + k;
        s[SP(base)]         = y0;
        s[SP(base + Q)]     = cmul(y1, tw[ti]);
        s[SP(base + 2 * Q)] = cmul(y2, tw[ti + NTWW]);
        s[SP(base + 3 * Q)] = cmul(y3, tw[ti + 2 * NTWW]);
        __syncthreads();
    }

    if (tid < 128) {
        const float RT = 0.70710678118654752f;
        float2 v[8];
        const int e0 = tid * 8;
        #pragma unroll
        for (int i = 0; i < 8; ++i) v[i] = s[SP(e0 + i)];

        {
            float2 A = make_float2(v[0].x + v[4].x, v[0].y + v[4].y);
            float2 B = make_float2(v[0].x - v[4].x, v[0].y - v[4].y);
            float2 C = make_float2(v[2].x + v[6].x, v[2].y + v[6].y);
            float2 D = make_float2(v[2].x - v[6].x, v[2].y - v[6].y);
            v[0] = make_float2(A.x + C.x, A.y + C.y);
            v[2] = make_float2(B.x + D.y, B.y - D.x);
            v[4] = make_float2(A.x - C.x, A.y - C.y);
            v[6] = make_float2(B.x - D.y, B.y + D.x);
        }
        {
            float2 A = make_float2(v[1].x + v[5].x, v[1].y + v[5].y);
            float2 B = make_float2(v[1].x - v[5].x, v[1].y - v[5].y);
            float2 C = make_float2(v[3].x + v[7].x, v[3].y + v[7].y);
            float2 D = make_float2(v[3].x - v[7].x, v[3].y - v[7].y);
            float2 y1 = make_float2(B.x + D.y, B.y - D.x);
            float2 y2 = make_float2(A.x - C.x, A.y - C.y);
            float2 y3 = make_float2(B.x - D.y, B.y + D.x);
            v[1] = make_float2(A.x + C.x, A.y + C.y);
            v[3] = make_float2((y1.x + y1.y) * RT, (y1.y - y1.x) * RT);
            v[5] = make_float2(y2.y, -y2.x);
            v[7] = make_float2((y3.y - y3.x) * RT, -(y3.x + y3.y) * RT);
        }
        #pragma unroll
        for (int i = 0; i < 4; ++i) {
            float2 a = v[2 * i], b = v[2 * i + 1];
            v[2 * i]     = make_float2(a.x + b.x, a.y + b.y);
            v[2 * i + 1] = make_float2(a.x - b.x, a.y - b.y);
        }
        #pragma unroll
        for (int i = 0; i < 8; ++i) s[SP(e0 + i)] = v[i];
    }
    __syncthreads();

    float2* w = g_W + (size_t)sgn * NBINS;
    for (int k = 2 * tid + half; k <= N2 / 2; k += 2 * WH_THREADS) {
        int m  = k;
        int mc = (N2 - k) & (N2 - 1);
        float2 Zk = s[SP(((m  & 3) >> 1) * 512 + perm512(m  >> 2))];
        float2 Zc = s[SP(((mc & 3) >> 1) * 512 + perm512(mc >> 2))];

        float Ax = Zk.x + Zc.x, Ay = Zk.y - Zc.y;
        float Bx = Zk.x - Zc.x, By = Zk.y + Zc.y;

        float sn, cs;
        __sincosf(-3.14159265358979323846f * (float)k / (float)N2, &sn, &cs);
        float t1 = cs * By + sn * Bx;
        float t2 = cs * Bx - sn * By;

        float X0x = Ax + t1, X0y = Ay - t2;
        float X1x = Ax - t1, X1y = -(Ay + t2);

        float i0 = rsqrtf(X0x * X0x + X0y * X0y + 1e-24f);
        float i1 = rsqrtf(X1x * X1x + X1y * X1y + 1e-24f);
        w[k]      = make_float2(X0x * i0, X0y * i0);
        w[N2 - k] = make_float2(X1x * i1, X1y * i1);
    }

    if (tid == 0) pdl_trigger();
}

// ===========================================================================
// 4096-pt radix-4 DIF inverse FFT: single W^1 table; W^2,W^3 via cmul. (r14)
// ===========================================================================
__device__ __forceinline__ void gen_twiddles(float2* tw, int tid)
{
    for (int k = tid; k < NTW; k += FFT_THREADS) {
        float th = -3.14159265358979323846f * (float)k / 2048.0f;
        float s1, c1;
        __sincosf(th, &s1, &c1);
        tw[k] = make_float2(c1, s1);
    }
}

__device__ __forceinline__ void ifft4096_dif(float2* s, const float2* tw, int tid)
{
    #pragma unroll
    for (int st = 0; st < 4; ++st) {
        const int lg = 10 - 2 * st;
        const int Q  = 1 << lg;
        #pragma unroll
        for (int u = 0; u < 2; ++u) {
            int j    = tid + u * FFT_THREADS;
            int k    = j & (Q - 1);
            int base = ((j >> lg) << (lg + 2)) + k;

            float2 a0 = s[SP(base)];
            float2 a1 = s[SP(base + Q)];
            float2 a2 = s[SP(base + 2 * Q)];
            float2 a3 = s[SP(base + 3 * Q)];

            float2 A = make_float2(a0.x + a2.x, a0.y + a2.y);
            float2 B = make_float2(a0.x - a2.x, a0.y - a2.y);
            float2 C = make_float2(a1.x + a3.x, a1.y + a3.y);
            float2 D = make_float2(a1.x - a3.x, a1.y - a3.y);

            float2 y0 = make_float2(A.x + C.x, A.y + C.y);
            float2 y1 = make_float2(B.x - D.y, B.y + D.x);
            float2 y2 = make_float2(A.x - C.x, A.y - C.y);
            float2 y3 = make_float2(B.x + D.y, B.y - D.x);

            float2 w1 = tw[k << (2 * st)];
            w1.y = -w1.y;
            float2 w2 = cmul(w1, w1);
            float2 w3 = cmul(w2, w1);

            s[SP(base)]         = y0;
            s[SP(base + Q)]     = cmul(y1, w1);
            s[SP(base + 2 * Q)] = cmul(y2, w2);
            s[SP(base + 3 * Q)] = cmul(y3, w3);
        }
        __syncthreads();
    }

    if (tid < 256) {
        const float CS[10] = { 1.f,  0.92387953f,  0.70710678f,  0.38268343f,  0.f,
                              -0.38268343f, -0.70710678f, -0.92387953f, -1.f, -0.92387953f};
        const float SN[10] = { 0.f, -0.38268343f, -0.70710678f, -0.92387953f, -1.f,
                              -0.92387953f, -0.70710678f, -0.38268343f,  0.f,  0.38268343f};
        const float sg = -1.0f;
        float2 v[16];
        const int e0 = 16 * tid;
        #pragma unroll
        for (int m = 0; m < 16; ++m) v[m] = s[SP(e0 + m)];

        #pragma unroll
        for (int m = 0; m < 4; ++m) {
            float2 p = v[m], q = v[m + 4], r = v[m + 8], w = v[m + 12];
            float2 A = make_float2(p.x + r.x, p.y + r.y);
            float2 B = make_float2(p.x - r.x, p.y - r.y);
            float2 C = make_float2(q.x + w.x, q.y + w.y);
            float2 D = make_float2(q.x - w.x, q.y - w.y);
            float2 y0 = make_float2(A.x + C.x, A.y + C.y);
            float2 y1 = make_float2(B.x + sg * D.y, B.y - sg * D.x);
            float2 y2 = make_float2(A.x - C.x, A.y - C.y);
            float2 y3 = make_float2(B.x - sg * D.y, B.y + sg * D.x);
            float2 w1 = make_float2(CS[m],     sg * SN[m]);
            float2 w2 = make_float2(CS[2 * m], sg * SN[2 * m]);
            float2 w3 = make_float2(CS[3 * m], sg * SN[3 * m]);
            v[m]      = y0;
            v[m + 4]  = cmul(y1, w1);
            v[m + 8]  = cmul(y2, w2);
            v[m + 12] = cmul(y3, w3);
        }
        #pragma unroll
        for (int h = 0; h < 4; ++h) {
            float2 p = v[4*h], q = v[4*h+1], r = v[4*h+2], w = v[4*h+3];
            float2 A = make_float2(p.x + r.x, p.y + r.y);
            float2 B = make_float2(p.x - r.x, p.y - r.y);
            float2 C = make_float2(q.x + w.x, q.y + w.y);
            float2 D = make_float2(q.x - w.x, q.y - w.y);
            v[4*h]   = make_float2(A.x + C.x, A.y + C.y);
            v[4*h+1] = make_float2(B.x + sg * D.y, B.y - sg * D.x);
            v[4*h+2] = make_float2(A.x - C.x, A.y - C.y);
            v[4*h+3] = make_float2(B.x - sg * D.y, B.y + sg * D.x);
        }
        #pragma unroll
        for (int m = 0; m < 16; ++m) s[SP(e0 + m)] = v[m];
    }
    __syncthreads();
}

// ===========================================================================
// Kernel 2: cross-spectrum + inverse FFT, two pairs per iFFT. (r14, proven)
// ===========================================================================
__global__ void __launch_bounds__(FFT_THREADS) k_xcorr(const int* __restrict__ comb)
{
    extern __shared__ float2 dyn[];
    float2* s  = dyn;
    float2* tw = dyn + SMEM_PAD;

    const int tid = threadIdx.x;
    if (blockIdx.x == 0 && tid == 0) {
        g_done = 0;
        #pragma unroll
        for (int b = 0; b < BATCH; ++b) g_best[b] = 0ull;
    }

    const int q0 = blockIdx.x * 2, q1 = q0 + 1;
    const int b0 = q0 / NPAIR, p0 = q0 % NPAIR;
    const int b1 = q1 / NPAIR, p1 = q1 % NPAIR;

    const int ia0 = comb[2 * p0], ib0 = comb[2 * p0 + 1];
    const int ia1 = comb[2 * p1], ib1 = comb[2 * p1 + 1];

    gen_twiddles(tw, tid);          // overlaps with whiten via PDL

    pdl_wait();

    const float2* Wa0 = g_W + (size_t)(b0 * NMICS + ia0) * NBINS;
    const float2* Wb0 = g_W + (size_t)(b0 * NMICS + ib0) * NBINS;
    const float2* Wa1 = g_W + (size_t)(b1 * NMICS + ia1) * NBINS;
    const float2* Wb1 = g_W + (size_t)(b1 * NMICS + ib1) * NBINS;

    for (int k = tid; k <= N_FFT / 2; k += FFT_THREADS) {
        float2 a0 = Wa0[k], c0 = Wb0[k];
        float x1r = a0.x * c0.x + a0.y * c0.y;
        float x1i = a0.y * c0.x - a0.x * c0.y;
        float2 a1 = Wa1[k], c1 = Wb1[k];
        float x2r = a1.x * c1.x + a1.y * c1.y;
        float x2i = a1.y * c1.x - a1.x * c1.y;

        s[SP(k)] = make_float2(x1r - x2i, x1i + x2r);
        if (k > 0 && k < N_FFT / 2)
            s[SP(N_FFT - k)] = make_float2(x1r + x2i, x2r - x1i);
    }
    __syncthreads();

    ifft4096_dif(s, tw, tid);

    if (tid < NLAG) {
        int idx = (tid + (N_FFT - 40)) & (N_FFT - 1);
        float2 v = s[SP(dr12(idx))];
        g_cc[(p0 * NLAG + tid) * BATCH + b0] = v.x;
        g_cc[(p1 * NLAG + tid) * BATCH + b1] = v.y;
    }

    if (tid == 0) pdl_trigger();
}

// ===========================================================================
// Kernel 3: SRP accumulation + argmax + fused final decode.
// 512 threads / 64 grid points per block (491 blocks): halves per-block
// epilogue cost (g_best atomics, ticket, barriers) vs the 256-thread build.
// tau prefetched into 16B-aligned smem BEFORE pdl_wait (r16, proven).
// ===========================================================================
__device__ __forceinline__ unsigned int fkey(float f)
{
    unsigned int b = __float_as_uint(f);
    return (b & 0x80000000u) ? ~b : (b | 0x80000000u);
}

__global__ void __launch_bounds__(SRP_THREADS) k_srp(const int* __restrict__ tau, int G,
                                                     const float* __restrict__ grid_x,
                                                     const float* __restrict__ cen,
                                                     float* __restrict__ out)
{
    __shared__ unsigned long long sbest[BATCH];
    __shared__ int s_last;
    __shared__ __align__(16) int s_tau[64 * NPAIR];   // 64 pts x 28 taus (7 KB)

    const int tid = threadIdx.x;
    if (tid < BATCH) sbest[tid] = 0ull;
    if (tid == 0) s_last = 0;

    const int g0 = blockIdx.x * 64;          // first grid point of this block

    // prefetch tau (independent of xcorr) — issues before the PDL wait
    if (tid < 64 * (NPAIR / 4)) {            // 448 threads: row = tid/7, q = tid%7
        int row = tid / 7;
        int q   = tid - row * 7;
        int g   = g0 + row;
        if (g < G) {
            int4 v = ((const int4*)(tau + (size_t)g * NPAIR))[q];
            *(int4*)(s_tau + row * NPAIR + q * 4) = v;
        }
    }

    pdl_wait();                              // g_cc ready beyond here
    __syncthreads();                         // s_tau ready

    const int lg = tid >> 3;                 // local grid point 0..63
    const int g  = g0 + lg;
    const int bp = tid & 7;                  // batches 2bp, 2bp+1

    unsigned long long k0 = 0ull, k1 = 0ull;

    if (g < G) {
        float2 pw = make_float2(0.0f, 0.0f);
        const int* trow = s_tau + lg * NPAIR;
        #pragma unroll
        for (int p = 0; p < NPAIR; ++p) {
            float2 r = *(const float2*)(g_cc + (p * NLAG + trow[p]) * BATCH + bp * 2);
            pw.x += r.x; pw.y += r.y;
        }
        const unsigned int gk = ~(unsigned int)g;
        k0 = ((unsigned long long)fkey(pw.x) << 32) | gk;
        k1 = ((unsigned long long)fkey(pw.y) << 32) | gk;
    }

    #pragma unroll
    for (int off = 8; off < 32; off <<= 1) {
        unsigned long long o0 = __shfl_xor_sync(0xFFFFFFFFu, k0, off);
        unsigned long long o1 = __shfl_xor_sync(0xFFFFFFFFu, k1, off);
        if (o0 > k0) k0 = o0;
        if (o1 > k1) k1 = o1;
    }
    if ((tid & 31) < 8) {
        atomicMax(&sbest[bp * 2],     k0);
        atomicMax(&sbest[bp * 2 + 1], k1);
    }
    __syncthreads();

    if (tid < BATCH) {
        atomicMax(&g_best[tid], sbest[tid]);
        __threadfence();
    }
    __syncthreads();
    if (tid == 0) {
        int ticket = atomicAdd(&g_done, 1);
        if (ticket == (int)gridDim.x - 1) { __threadfence(); s_last = 1; }
    }
    __syncthreads();
    if (s_last && tid < BATCH) {
        unsigned long long v = atomicMax(&g_best[tid], 0ull);
        unsigned int idx = ~(unsigned int)(v & 0xFFFFFFFFull);
        #pragma unroll
        for (int j = 0; j < 3; ++j)
            out[tid * 3 + j] = grid_x[(size_t)idx * 3 + j] - cen[j];
    }
}

// ---------------------------------------------------------------------------
extern "C" void kernel_launch(void* const* d_in, const int* in_sizes, int n_in,
                              void* d_out, int out_size)
{
    const float* signal = (const float*)d_in[0];
    const float* grid_x = (const float*)d_in[1];
    const int*   tau    = (const int*)d_in[2];
    const int*   comb   = (const int*)d_in[3];
    const float* cen    = (const float*)d_in[4];

    const int G = in_sizes[1] / 3;

    cudaFuncSetAttribute(k_xcorr, cudaFuncAttributeMaxDynamicSharedMemorySize,
                         (int)XC_SMEM);

    // primary: split whiten (256 blocks x 256 threads)
    k_fft_whiten<<<BATCH * NMICS * 2, WH_THREADS, WH_SMEM>>>(signal);

    // dependents: PDL — prologue overlaps primary; wait gates the data reads.
    cudaLaunchAttribute attr[1];
    attr[0].id = cudaLaunchAttributeProgrammaticStreamSerialization;
    attr[0].val.programmaticStreamSerializationAllowed = 1;

    {
        cudaLaunchConfig_t cfg = {};
        cfg.gridDim  = dim3(BATCH * NPAIR / 2, 1, 1);
        cfg.blockDim = dim3(FFT_THREADS, 1, 1);
        cfg.dynamicSmemBytes = XC_SMEM;
        cfg.stream = 0;
        cfg.attrs = attr;
        cfg.numAttrs = 1;
        cudaLaunchKernelEx(&cfg, k_xcorr, comb);
    }
    {
        cudaLaunchConfig_t cfg = {};
        cfg.gridDim  = dim3((G + 63) / 64, 1, 1);
        cfg.blockDim = dim3(SRP_THREADS, 1, 1);
        cfg.dynamicSmemBytes = 0;
        cfg.stream = 0;
        cfg.attrs = attr;
        cfg.numAttrs = 1;
        cudaLaunchKernelEx(&cfg, k_srp, tau, G, grid_x, cen, (float*)d_out);
    }
}